// round 4
// baseline (speedup 1.0000x reference)
#include <cuda_runtime.h>
#include <cuda_bf16.h>
#include <math.h>

#define NN 512
#define NBATCH 128
#define EPS 1e-8f
#define S_CAP 304
#define PK_CAP ((S_CAP*(S_CAP+1))/2)      /* 46360 floats = 185440 B */
#define PBW_SM (S_CAP-32)                  /* 272, multiple of 8 */
#define PK_FULL ((NN*(NN+1))/2)           /* 131328 floats */
#define NTB 256                            /* k_batch threads */
#define NWB 8
#define NT 512                             /* k_zpanel threads */
#define NW 16
#define DYN_B ((PK_CAP + 32*PBW_SM)*4)    /* 220256 B */

// ---------------- device scratch (no allocations allowed) ----------------
__device__ float g_L[NN*NN];       // L = B^T B + eps I
__device__ float g_Z[NN*NN];       // Z = L + I, Cholesky-factored in place
__device__ float g_zpart[8];
__device__ float g_bres[NBATCH];
__device__ __align__(16) float g_fbA[(size_t)NBATCH * PK_FULL];   // fallback packed A
__device__ __align__(16) float g_fbPB[(size_t)NBATCH * 32 * NN];  // fallback panel buf

// =====================================================================
// K1: L = B^T B + eps I ; Z = L + I.
// =====================================================================
__global__ __launch_bounds__(256) void k_gemm(const float* __restrict__ B)
{
    __shared__ float SA[16][64];
    __shared__ float SB[16][64];
    const int tid = threadIdx.x;
    const int tx = tid & 15, ty = tid >> 4;
    const int i0 = blockIdx.y * 64, j0 = blockIdx.x * 64;

    float acc[4][4];
#pragma unroll
    for (int r = 0; r < 4; ++r)
#pragma unroll
        for (int c = 0; c < 4; ++c) acc[r][c] = 0.f;

    for (int kc = 0; kc < NN; kc += 16) {
        for (int e = tid; e < 16*64; e += 256) {
            int kk = e >> 6, ii = e & 63;
            SA[kk][ii] = B[(kc+kk)*NN + i0 + ii];
            SB[kk][ii] = B[(kc+kk)*NN + j0 + ii];
        }
        __syncthreads();
#pragma unroll
        for (int kk = 0; kk < 16; ++kk) {
            float a[4], bb[4];
#pragma unroll
            for (int r = 0; r < 4; ++r) a[r]  = SA[kk][ty*4 + r];
#pragma unroll
            for (int c = 0; c < 4; ++c) bb[c] = SB[kk][tx*4 + c];
#pragma unroll
            for (int r = 0; r < 4; ++r)
#pragma unroll
                for (int c = 0; c < 4; ++c) acc[r][c] += a[r] * bb[c];
        }
        __syncthreads();
    }
#pragma unroll
    for (int r = 0; r < 4; ++r)
#pragma unroll
        for (int c = 0; c < 4; ++c) {
            int gi = i0 + ty*4 + r, gj = j0 + tx*4 + c;
            float v = acc[r][c] + ((gi == gj) ? EPS : 0.f);
            g_L[gi*NN + gj] = v;
            g_Z[gi*NN + gj] = v + ((gi == gj) ? 1.f : 0.f);
        }
}

// =====================================================================
// Per-batch blocked Cholesky. 256 threads (8 warps), nb=32.
//  A: warp0 factors diag block in registers (shfl)
//  B: per-thread row solve (row in regs), results -> PB transposed
//  C: SYRK trailing from PB, 8x4 register tiles, float4 LDS
// =====================================================================
__global__ __launch_bounds__(NTB) void k_batch(const int* __restrict__ x)
{
    extern __shared__ float dynsm[];
    __shared__ int   sidx[NN];
    __shared__ short spos[NN];
    __shared__ unsigned char sact[NN];
    __shared__ float s_inv[32];
    __shared__ int   s_rbD[32];
    __shared__ int   s_sh;

    const int b = blockIdx.x;
    const int tid = threadIdx.x, warp = tid >> 5, lane = tid & 31;

    // active index list + inverse position map (warp 0)
    if (tid < 32) {
        int cnt = 0;
        for (int base = 0; base < NN; base += 32) {
            int g = base + lane;
            int v = (x[b*NN + g] != 0);
            unsigned m = __ballot_sync(0xffffffffu, v);
            int p = cnt + __popc(m & ((1u << lane) - 1u));
            if (v) sidx[p] = g;
            spos[g] = (short)p;
            sact[g] = (unsigned char)v;
            cnt += __popc(m);
        }
        if (lane == 0) s_sh = cnt;
    }
    __syncthreads();
    const int s = s_sh;
    const bool fits = (s <= S_CAP);
    float* A  = fits ? dynsm            : &g_fbA [(size_t)b * PK_FULL];
    float* PB = fits ? (dynsm + PK_CAP) : &g_fbPB[(size_t)b * 32 * NN];
    const int pbw = fits ? PBW_SM : NN;

    // gather: coalesced row read + compacting scatter into packed lower
    for (int i = warp; i < s; i += NWB) {
        const float* Lrow = &g_L[sidx[i] * NN];
        const int rb = (i * (i + 1)) >> 1;
        const int glim = sidx[i] + 1;          // cols j<=i correspond to g < glim
        for (int g = lane; g < glim; g += 32) {
            float v = Lrow[g];
            if (sact[g]) A[rb + spos[g]] = v;
        }
    }
    __syncthreads();

    float lsum = 0.f;                           // valid on tid 0
    for (int j0 = 0; j0 < s; j0 += 32) {
        const int nbj = (s - j0 < 32) ? (s - j0) : 32;
        if (tid < nbj)
            s_rbD[tid] = (((j0 + tid) * (j0 + tid + 1)) >> 1) + j0;
        __syncthreads();

        // ---- Phase A: warp0 factors diag block in registers ----
        if (warp == 0) {
            const int row = j0 + lane;
            const bool act = (lane < nbj);
            int rbI = 0;
            if (act) rbI = (row * (row + 1)) >> 1;
            float v[32];
#pragma unroll
            for (int k = 0; k < 32; ++k)
                v[k] = (act && k <= lane && k < nbj) ? A[rbI + j0 + k] : 0.f;

            for (int j = 0; j < nbj; ++j) {
                float dj = __shfl_sync(0xffffffffu, v[j], j);
                float d = sqrtf(dj);
                float inv = 1.f / d;
                if (lane == j) { v[j] = d; s_inv[j] = inv; }
                else if (lane > j) v[j] *= inv;
                float cj = (act && lane > j) ? v[j] : 0.f;
                for (int k = j + 1; k < nbj; ++k) {
                    float cjk = __shfl_sync(0xffffffffu, cj, k);
                    if (lane >= k) v[k] -= cj * cjk;
                }
                if (lane == 0) lsum += logf(d);
            }
#pragma unroll
            for (int k = 0; k < 32; ++k)
                if (act && k <= lane && k < nbj) A[rbI + j0 + k] = v[k];
        }
        __syncthreads();

        const int j1 = j0 + 32;
        if (j1 >= s) break;                     // uniform
        const int nrows = s - j1;

        // ---- Phase B: triangular solve; write solved rows transposed to PB ----
        for (int i = j1 + tid; i < s; i += NTB) {
            const int rbI = (i * (i + 1)) >> 1;
            float v[32];
#pragma unroll
            for (int j = 0; j < 32; ++j) v[j] = A[rbI + j0 + j];
#pragma unroll
            for (int j = 0; j < 32; ++j) {
                float acc0 = v[j], acc1 = 0.f;
                const float* dr = &A[s_rbD[j]];
                int m = 0;
                for (; m + 1 < j; m += 2) {
                    acc0 -= v[m]   * dr[m];
                    acc1 -= v[m+1] * dr[m+1];
                }
                if (m < j) acc0 -= v[m] * dr[m];
                v[j] = (acc0 + acc1) * s_inv[j];
            }
            const int col = i - j1;
#pragma unroll
            for (int j = 0; j < 32; ++j) PB[j * pbw + col] = v[j];
        }
        __syncthreads();

        // ---- Phase C: SYRK trailing from PB, 8x4 tiles ----
        const int RT = (nrows + 7) >> 3;
        for (int ti = warp; ti < RT; ti += NWB) {
            const int ar = 8 * ti;
            const int ktmax = 2 * ti + 2;
            for (int kt = lane; kt < ktmax; kt += 32) {
                const int bc = 4 * kt;
                float acc[8][4];
#pragma unroll
                for (int qr = 0; qr < 8; ++qr)
#pragma unroll
                    for (int qc = 0; qc < 4; ++qc) acc[qr][qc] = 0.f;
#pragma unroll
                for (int j = 0; j < 32; ++j) {
                    const float* pr = &PB[j * pbw];
                    float4 a0 = *(const float4*)&pr[ar];
                    float4 a1 = *(const float4*)&pr[ar + 4];
                    float4 bv = *(const float4*)&pr[bc];
                    float av[8] = {a0.x,a0.y,a0.z,a0.w,a1.x,a1.y,a1.z,a1.w};
                    float bb[4] = {bv.x,bv.y,bv.z,bv.w};
#pragma unroll
                    for (int qr = 0; qr < 8; ++qr)
#pragma unroll
                        for (int qc = 0; qc < 4; ++qc)
                            acc[qr][qc] += av[qr] * bb[qc];
                }
#pragma unroll
                for (int qr = 0; qr < 8; ++qr) {
                    const int r = j1 + ar + qr;
                    if (r < s) {
                        const int rb = (r * (r + 1)) >> 1;
#pragma unroll
                        for (int qc = 0; qc < 4; ++qc) {
                            const int c = j1 + bc + qc;
                            if (c <= r) A[rb + c] -= acc[qr][qc];
                        }
                    }
                }
            }
        }
        __syncthreads();
    }
    if (tid == 0) g_bres[b] = 2.f * lsum;
}

// =====================================================================
// Z chain (unchanged from R3): panel-64 in smem + multi-CTA trailing.
// =====================================================================
__global__ __launch_bounds__(NT) void k_zpanel(int p)
{
    extern __shared__ float T[];              // nr x 65
    __shared__ float s_inv[32];
    const int nr = NN - 64 * p;
    const int tid = threadIdx.x, warp = tid >> 5, lane = tid & 31;

    for (int r = warp; r < nr; r += NW) {
        const float* src = &g_Z[(64*p + r)*NN + 64*p];
        float* dst = &T[r*65];
        for (int j = lane; j < 64; j += 32) dst[j] = src[j];
    }
    __syncthreads();

    float lsum = 0.f;
    for (int cb = 0; cb < 64; cb += 32) {
        if (warp == 0) {
            float v[32];
#pragma unroll
            for (int k = 0; k < 32; ++k)
                v[k] = (k <= lane) ? T[(cb+lane)*65 + cb + k] : 0.f;
            for (int j = 0; j < 32; ++j) {
                float dj = __shfl_sync(0xffffffffu, v[j], j);
                float d = sqrtf(dj);
                float inv = 1.f / d;
                if (lane == j) { v[j] = d; s_inv[j] = inv; }
                else if (lane > j) v[j] *= inv;
                float cj = (lane > j) ? v[j] : 0.f;
                for (int k = j + 1; k < 32; ++k) {
                    float cjk = __shfl_sync(0xffffffffu, cj, k);
                    if (lane >= k) v[k] -= cj * cjk;
                }
                if (lane == 0) lsum += logf(d);
            }
#pragma unroll
            for (int k = 0; k < 32; ++k)
                if (k <= lane) T[(cb+lane)*65 + cb + k] = v[k];
        }
        __syncthreads();

        const int r1 = cb + 32;
        for (int i = r1 + tid; i < nr; i += NT) {
            float* row = &T[i*65 + cb];
            float v[32];
#pragma unroll
            for (int j = 0; j < 32; ++j) v[j] = row[j];
#pragma unroll
            for (int j = 0; j < 32; ++j) {
                float acc0 = v[j], acc1 = 0.f;
                const float* dr = &T[(cb+j)*65 + cb];
                int m = 0;
                for (; m + 1 < j; m += 2) {
                    acc0 -= v[m]   * dr[m];
                    acc1 -= v[m+1] * dr[m+1];
                }
                if (m < j) acc0 -= v[m] * dr[m];
                v[j] = (acc0 + acc1) * s_inv[j];
            }
#pragma unroll
            for (int j = 0; j < 32; ++j) row[j] = v[j];
        }
        __syncthreads();

        if (cb == 0) {
            const int nrows = nr - 32;
            const int RT = (nrows + 15) >> 4;
            const int sub = lane >> 3;
            const int ktc = lane & 7;
            for (int ti = warp; ti < RT; ti += NW) {
                const int r0 = 32 + ti*16 + sub*4;
                const int c0 = 32 + ktc*4;
                float acc[4][4];
#pragma unroll
                for (int qr = 0; qr < 4; ++qr)
#pragma unroll
                    for (int qc = 0; qc < 4; ++qc) acc[qr][qc] = 0.f;
#pragma unroll
                for (int j = 0; j < 32; ++j) {
                    float a[4], bb[4];
#pragma unroll
                    for (int q = 0; q < 4; ++q) {
                        int r = r0 + q; if (r > nr - 1) r = nr - 1;
                        a[q] = T[r*65 + j];
                    }
#pragma unroll
                    for (int q = 0; q < 4; ++q) bb[q] = T[(c0+q)*65 + j];
#pragma unroll
                    for (int qr = 0; qr < 4; ++qr)
#pragma unroll
                        for (int qc = 0; qc < 4; ++qc)
                            acc[qr][qc] += a[qr] * bb[qc];
                }
#pragma unroll
                for (int qr = 0; qr < 4; ++qr) {
                    const int r = r0 + qr;
#pragma unroll
                    for (int qc = 0; qc < 4; ++qc) {
                        const int c = c0 + qc;
                        if (r < nr && c <= r)
                            T[r*65 + c] -= acc[qr][qc];
                    }
                }
            }
        }
        __syncthreads();
    }

    for (int r = warp; r < nr; r += NW) {
        float* dst = &g_Z[(64*p + r)*NN + 64*p];
        int jmax = (r < 63) ? r : 63;
        for (int j = lane; j <= jmax; j += 32) dst[j] = T[r*65 + j];
    }
    if (tid == 0) g_zpart[p] = 2.f * lsum;
}

__global__ __launch_bounds__(256) void k_ztrail(int p)
{
    __shared__ float As[64][65];
    __shared__ float Bs[64][65];
    int l = blockIdx.x, bi = 0, bj = 0;
    for (int q = p + 1; q <= 7; ++q) {
        int c = 8 - q;
        if (l < c) { bj = q; bi = q + l; break; }
        l -= c;
    }
    const int tid = threadIdx.x;
    const int tx = tid & 15, ty = tid >> 4;

    for (int e = tid; e < 64*64; e += 256) {
        int i = e >> 6, k = e & 63;
        As[i][k] = g_Z[(64*bi + i)*NN + 64*p + k];
    }
    for (int e = tid; e < 64*64; e += 256) {
        int i = e >> 6, k = e & 63;
        Bs[i][k] = g_Z[(64*bj + i)*NN + 64*p + k];
    }
    __syncthreads();

    float acc[4][4];
#pragma unroll
    for (int r = 0; r < 4; ++r)
#pragma unroll
        for (int c = 0; c < 4; ++c) acc[r][c] = 0.f;

    for (int k = 0; k < 64; ++k) {
        float a[4], bb[4];
#pragma unroll
        for (int r = 0; r < 4; ++r) a[r]  = As[ty*4 + r][k];
#pragma unroll
        for (int c = 0; c < 4; ++c) bb[c] = Bs[tx*4 + c][k];
#pragma unroll
        for (int r = 0; r < 4; ++r)
#pragma unroll
            for (int c = 0; c < 4; ++c) acc[r][c] += a[r] * bb[c];
    }
#pragma unroll
    for (int r = 0; r < 4; ++r)
#pragma unroll
        for (int c = 0; c < 4; ++c)
            g_Z[(64*bi + ty*4 + r)*NN + 64*bj + tx*4 + c] -= acc[r][c];
}

// =====================================================================
__global__ void k_combine(float* __restrict__ out)
{
    __shared__ float z;
    if (threadIdx.x == 0) {
        float t = 0.f;
        for (int p = 0; p < 8; ++p) t += g_zpart[p];
        z = t;
    }
    __syncthreads();
    if (threadIdx.x < NBATCH)
        out[threadIdx.x] = g_bres[threadIdx.x] - z;
}

// =====================================================================
extern "C" void kernel_launch(void* const* d_in, const int* in_sizes, int n_in,
                              void* d_out, int out_size)
{
    const int* x = (const int*)d_in[0];
    const float* Bm = (const float*)d_in[1];
    if (in_sizes[0] == NN*NN && in_sizes[1] == NBATCH*NN) {
        x  = (const int*)d_in[1];
        Bm = (const float*)d_in[0];
    }
    float* out = (float*)d_out;

    cudaFuncSetAttribute(k_batch,  cudaFuncAttributeMaxDynamicSharedMemorySize, DYN_B);
    cudaFuncSetAttribute(k_zpanel, cudaFuncAttributeMaxDynamicSharedMemorySize, NN*65*4);

    // Launch order chosen so k_batch is the 6th launch (ncu -s 5 -c 1 profiles it).
    k_gemm<<<dim3(8,8), 256>>>(Bm);                         // 1
    for (int p = 0; p < 2; ++p) {                           // 2..5
        int nr = NN - 64*p;
        k_zpanel<<<1, NT, nr*65*4>>>(p);
        k_ztrail<<<(7-p)*(8-p)/2, 256>>>(p);
    }
    k_batch<<<NBATCH, NTB, DYN_B>>>(x);                     // 6  <-- profiled
    for (int p = 2; p < 8; ++p) {
        int nr = NN - 64*p;
        k_zpanel<<<1, NT, nr*65*4>>>(p);
        int m = 7 - p;
        if (m > 0) k_ztrail<<<m*(m+1)/2, 256>>>(p);
    }
    k_combine<<<1, 128>>>(out);
}

// round 6
// speedup vs baseline: 1.5356x; 1.5356x over previous
#include <cuda_runtime.h>
#include <cuda_bf16.h>
#include <math.h>

#define NN 512
#define NBATCH 128
#define EPS 1e-8f
#define S_CAP 304
#define PK_CAP ((S_CAP*(S_CAP+1))/2)      /* 46360 floats = 185440 B */
#define PBW_SM (S_CAP-32)                  /* 272 */
#define PK_FULL ((NN*(NN+1))/2)
#define NTB 256                            /* k_batch threads */
#define NWB 8
#define NT 512                             /* k_zpanel threads */
#define NW 16
#define DYN_B ((PK_CAP + 32*PBW_SM)*4)    /* 220256 B */

// ---------------- device scratch ----------------
__device__ float g_L[NN*NN];
__device__ float g_Z[NN*NN];
__device__ float g_zpart[8];
__device__ float g_bres[NBATCH];
__device__ __align__(16) float g_fbA[(size_t)NBATCH * PK_FULL];
__device__ __align__(16) float g_fbPB[(size_t)NBATCH * 32 * NN];

// =====================================================================
// K1: L = B^T B + eps I ; Z = L + I.
// =====================================================================
__global__ __launch_bounds__(256) void k_gemm(const float* __restrict__ B)
{
    __shared__ float SA[16][64];
    __shared__ float SB[16][64];
    const int tid = threadIdx.x;
    const int tx = tid & 15, ty = tid >> 4;
    const int i0 = blockIdx.y * 64, j0 = blockIdx.x * 64;

    float acc[4][4];
#pragma unroll
    for (int r = 0; r < 4; ++r)
#pragma unroll
        for (int c = 0; c < 4; ++c) acc[r][c] = 0.f;

    for (int kc = 0; kc < NN; kc += 16) {
        for (int e = tid; e < 16*64; e += 256) {
            int kk = e >> 6, ii = e & 63;
            SA[kk][ii] = B[(kc+kk)*NN + i0 + ii];
            SB[kk][ii] = B[(kc+kk)*NN + j0 + ii];
        }
        __syncthreads();
#pragma unroll
        for (int kk = 0; kk < 16; ++kk) {
            float a[4], bb[4];
#pragma unroll
            for (int r = 0; r < 4; ++r) a[r]  = SA[kk][ty*4 + r];
#pragma unroll
            for (int c = 0; c < 4; ++c) bb[c] = SB[kk][tx*4 + c];
#pragma unroll
            for (int r = 0; r < 4; ++r)
#pragma unroll
                for (int c = 0; c < 4; ++c) acc[r][c] += a[r] * bb[c];
        }
        __syncthreads();
    }
#pragma unroll
    for (int r = 0; r < 4; ++r)
#pragma unroll
        for (int c = 0; c < 4; ++c) {
            int gi = i0 + ty*4 + r, gj = j0 + tx*4 + c;
            float v = acc[r][c] + ((gi == gj) ? EPS : 0.f);
            g_L[gi*NN + gj] = v;
            g_Z[gi*NN + gj] = v + ((gi == gj) ? 1.f : 0.f);
        }
}

// =====================================================================
// Per-batch blocked Cholesky (nb=32). Phase A fully unrolled (registers).
// =====================================================================
__global__ __launch_bounds__(NTB) void k_batch(const int* __restrict__ x)
{
    extern __shared__ float dynsm[];
    __shared__ int   sidx[NN];
    __shared__ short spos[NN];
    __shared__ unsigned char sact[NN];
    __shared__ float s_inv[32];
    __shared__ int   s_rbD[32];
    __shared__ int   s_sh;

    const int b = blockIdx.x;
    const int tid = threadIdx.x, warp = tid >> 5, lane = tid & 31;

    if (tid < 32) {
        int cnt = 0;
        for (int base = 0; base < NN; base += 32) {
            int g = base + lane;
            int v = (x[b*NN + g] != 0);
            unsigned m = __ballot_sync(0xffffffffu, v);
            int p = cnt + __popc(m & ((1u << lane) - 1u));
            if (v) sidx[p] = g;
            spos[g] = (short)p;
            sact[g] = (unsigned char)v;
            cnt += __popc(m);
        }
        if (lane == 0) s_sh = cnt;
    }
    __syncthreads();
    const int s = s_sh;
    const bool fits = (s <= S_CAP);
    float* A  = fits ? dynsm            : &g_fbA [(size_t)b * PK_FULL];
    float* PB = fits ? (dynsm + PK_CAP) : &g_fbPB[(size_t)b * 32 * NN];
    const int pbw = fits ? PBW_SM : NN;

    // gather: coalesced row read + compacting scatter
    for (int i = warp; i < s; i += NWB) {
        const float* Lrow = &g_L[sidx[i] * NN];
        const int rb = (i * (i + 1)) >> 1;
        const int glim = sidx[i] + 1;
        for (int g = lane; g < glim; g += 32) {
            float v = Lrow[g];
            if (sact[g]) A[rb + spos[g]] = v;
        }
    }
    __syncthreads();

    float lsum = 0.f;
    for (int j0 = 0; j0 < s; j0 += 32) {
        const int nbj = (s - j0 < 32) ? (s - j0) : 32;
        if (tid < nbj)
            s_rbD[tid] = (((j0 + tid) * (j0 + tid + 1)) >> 1) + j0;
        __syncthreads();

        // ---- Phase A: warp0, diag block, FULLY UNROLLED (registers) ----
        if (warp == 0) {
            const int row = j0 + lane;
            const bool act = (lane < nbj);
            const int rbI = act ? ((row * (row + 1)) >> 1) : 0;
            float v[32];
#pragma unroll
            for (int k = 0; k < 32; ++k)
                v[k] = (act && k <= lane && k < nbj) ? A[rbI + j0 + k] : 0.f;

#pragma unroll
            for (int j = 0; j < 32; ++j) {
                if (j >= nbj) break;
                float dj = __shfl_sync(0xffffffffu, v[j], j);
                float d = sqrtf(dj);
                float inv = 1.f / d;
                if (lane == j) { v[j] = d; s_inv[j] = inv; }
                else if (lane > j) v[j] *= inv;
                float cj = (lane > j) ? v[j] : 0.f;
#pragma unroll
                for (int k = j + 1; k < 32; ++k) {
                    float cjk = __shfl_sync(0xffffffffu, cj, k);
                    v[k] -= cj * cjk;   // lanes < k hold dead data; never read/written back
                }
                if (lane == 0) lsum += logf(d);
            }
#pragma unroll
            for (int k = 0; k < 32; ++k)
                if (act && k <= lane && k < nbj) A[rbI + j0 + k] = v[k];
        }
        __syncthreads();

        const int j1 = j0 + 32;
        if (j1 >= s) break;
        const int nrows = s - j1;

        // ---- Phase B: triangular solve; rows -> PB transposed ----
        for (int i = j1 + tid; i < s; i += NTB) {
            const int rbI = (i * (i + 1)) >> 1;
            float v[32];
#pragma unroll
            for (int j = 0; j < 32; ++j) v[j] = A[rbI + j0 + j];
#pragma unroll
            for (int j = 0; j < 32; ++j) {
                float acc0 = v[j], acc1 = 0.f;
                const float* dr = &A[s_rbD[j]];
#pragma unroll
                for (int m = 0; m + 1 < j; m += 2) {
                    acc0 -= v[m]   * dr[m];
                    acc1 -= v[m+1] * dr[m+1];
                }
                if (j & 1) acc0 -= v[j-1] * dr[j-1];
                v[j] = (acc0 + acc1) * s_inv[j];
            }
            const int col = i - j1;
#pragma unroll
            for (int j = 0; j < 32; ++j) PB[j * pbw + col] = v[j];
        }
        __syncthreads();

        // ---- Phase C: SYRK trailing from PB, 8x4 tiles, float4 LDS ----
        const int RT = (nrows + 7) >> 3;
        for (int ti = warp; ti < RT; ti += NWB) {
            const int ar = 8 * ti;
            const int ktmax = 2 * ti + 2;
            for (int kt = lane; kt < ktmax; kt += 32) {
                const int bc = 4 * kt;
                float acc[8][4];
#pragma unroll
                for (int qr = 0; qr < 8; ++qr)
#pragma unroll
                    for (int qc = 0; qc < 4; ++qc) acc[qr][qc] = 0.f;
#pragma unroll
                for (int j = 0; j < 32; ++j) {
                    const float* pr = &PB[j * pbw];
                    float4 a0 = *(const float4*)&pr[ar];
                    float4 a1 = *(const float4*)&pr[ar + 4];
                    float4 bv = *(const float4*)&pr[bc];
                    float av[8] = {a0.x,a0.y,a0.z,a0.w,a1.x,a1.y,a1.z,a1.w};
                    float bb[4] = {bv.x,bv.y,bv.z,bv.w};
#pragma unroll
                    for (int qr = 0; qr < 8; ++qr)
#pragma unroll
                        for (int qc = 0; qc < 4; ++qc)
                            acc[qr][qc] += av[qr] * bb[qc];
                }
#pragma unroll
                for (int qr = 0; qr < 8; ++qr) {
                    const int r = j1 + ar + qr;
                    if (r < s) {
                        const int rb = (r * (r + 1)) >> 1;
#pragma unroll
                        for (int qc = 0; qc < 4; ++qc) {
                            const int c = j1 + bc + qc;
                            if (c <= r) A[rb + c] -= acc[qr][qc];
                        }
                    }
                }
            }
        }
        __syncthreads();
    }
    if (tid == 0) g_bres[b] = 2.f * lsum;
}

// =====================================================================
// Z panel: Phase A fully unrolled (fixed 32, no predicates).
// =====================================================================
__global__ __launch_bounds__(NT) void k_zpanel(int p)
{
    extern __shared__ float T[];              // nr x 65
    __shared__ float s_inv[32];
    const int nr = NN - 64 * p;
    const int tid = threadIdx.x, warp = tid >> 5, lane = tid & 31;

    for (int r = warp; r < nr; r += NW) {
        const float* src = &g_Z[(64*p + r)*NN + 64*p];
        float* dst = &T[r*65];
        for (int j = lane; j < 64; j += 32) dst[j] = src[j];
    }
    __syncthreads();

    float lsum = 0.f;
    for (int cb = 0; cb < 64; cb += 32) {
        // ---- Phase A: fully unrolled diag block ----
        if (warp == 0) {
            float v[32];
#pragma unroll
            for (int k = 0; k < 32; ++k)
                v[k] = (k <= lane) ? T[(cb+lane)*65 + cb + k] : 0.f;
#pragma unroll
            for (int j = 0; j < 32; ++j) {
                float dj = __shfl_sync(0xffffffffu, v[j], j);
                float d = sqrtf(dj);
                float inv = 1.f / d;
                if (lane == j) { v[j] = d; s_inv[j] = inv; }
                else if (lane > j) v[j] *= inv;
                float cj = (lane > j) ? v[j] : 0.f;
#pragma unroll
                for (int k = j + 1; k < 32; ++k) {
                    float cjk = __shfl_sync(0xffffffffu, cj, k);
                    v[k] -= cj * cjk;
                }
                if (lane == 0) lsum += logf(d);
            }
#pragma unroll
            for (int k = 0; k < 32; ++k)
                if (k <= lane) T[(cb+lane)*65 + cb + k] = v[k];
        }
        __syncthreads();

        const int r1 = cb + 32;
        // ---- Phase B ----
        for (int i = r1 + tid; i < nr; i += NT) {
            float* row = &T[i*65 + cb];
            float v[32];
#pragma unroll
            for (int j = 0; j < 32; ++j) v[j] = row[j];
#pragma unroll
            for (int j = 0; j < 32; ++j) {
                float acc0 = v[j], acc1 = 0.f;
                const float* dr = &T[(cb+j)*65 + cb];
#pragma unroll
                for (int m = 0; m + 1 < j; m += 2) {
                    acc0 -= v[m]   * dr[m];
                    acc1 -= v[m+1] * dr[m+1];
                }
                if (j & 1) acc0 -= v[j-1] * dr[j-1];
                v[j] = (acc0 + acc1) * s_inv[j];
            }
#pragma unroll
            for (int j = 0; j < 32; ++j) row[j] = v[j];
        }
        __syncthreads();

        // ---- Phase C (cb==0): rank-32 update of cols 32..63 ----
        if (cb == 0) {
            const int nrows = nr - 32;
            const int RT = (nrows + 15) >> 4;
            const int sub = lane >> 3;
            const int ktc = lane & 7;
            for (int ti = warp; ti < RT; ti += NW) {
                const int r0 = 32 + ti*16 + sub*4;
                const int c0 = 32 + ktc*4;
                float acc[4][4];
#pragma unroll
                for (int qr = 0; qr < 4; ++qr)
#pragma unroll
                    for (int qc = 0; qc < 4; ++qc) acc[qr][qc] = 0.f;
#pragma unroll
                for (int j = 0; j < 32; ++j) {
                    float a[4], bb[4];
#pragma unroll
                    for (int q = 0; q < 4; ++q) {
                        int r = r0 + q; if (r > nr - 1) r = nr - 1;
                        a[q] = T[r*65 + j];
                    }
#pragma unroll
                    for (int q = 0; q < 4; ++q) bb[q] = T[(c0+q)*65 + j];
#pragma unroll
                    for (int qr = 0; qr < 4; ++qr)
#pragma unroll
                        for (int qc = 0; qc < 4; ++qc)
                            acc[qr][qc] += a[qr] * bb[qc];
                }
#pragma unroll
                for (int qr = 0; qr < 4; ++qr) {
                    const int r = r0 + qr;
#pragma unroll
                    for (int qc = 0; qc < 4; ++qc) {
                        const int c = c0 + qc;
                        if (r < nr && c <= r)
                            T[r*65 + c] -= acc[qr][qc];
                    }
                }
            }
        }
        __syncthreads();
    }

    for (int r = warp; r < nr; r += NW) {
        float* dst = &g_Z[(64*p + r)*NN + 64*p];
        int jmax = (r < 63) ? r : 63;
        for (int j = lane; j <= jmax; j += 32) dst[j] = T[r*65 + j];
    }
    if (tid == 0) g_zpart[p] = 2.f * lsum;
}

__global__ __launch_bounds__(256) void k_ztrail(int p)
{
    __shared__ float As[64][65];
    __shared__ float Bs[64][65];
    int l = blockIdx.x, bi = 0, bj = 0;
    for (int q = p + 1; q <= 7; ++q) {
        int c = 8 - q;
        if (l < c) { bj = q; bi = q + l; break; }
        l -= c;
    }
    const int tid = threadIdx.x;
    const int tx = tid & 15, ty = tid >> 4;

    for (int e = tid; e < 64*64; e += 256) {
        int i = e >> 6, k = e & 63;
        As[i][k] = g_Z[(64*bi + i)*NN + 64*p + k];
    }
    for (int e = tid; e < 64*64; e += 256) {
        int i = e >> 6, k = e & 63;
        Bs[i][k] = g_Z[(64*bj + i)*NN + 64*p + k];
    }
    __syncthreads();

    float acc[4][4];
#pragma unroll
    for (int r = 0; r < 4; ++r)
#pragma unroll
        for (int c = 0; c < 4; ++c) acc[r][c] = 0.f;

    for (int k = 0; k < 64; ++k) {
        float a[4], bb[4];
#pragma unroll
        for (int r = 0; r < 4; ++r) a[r]  = As[ty*4 + r][k];
#pragma unroll
        for (int c = 0; c < 4; ++c) bb[c] = Bs[tx*4 + c][k];
#pragma unroll
        for (int r = 0; r < 4; ++r)
#pragma unroll
            for (int c = 0; c < 4; ++c) acc[r][c] += a[r] * bb[c];
    }
#pragma unroll
    for (int r = 0; r < 4; ++r)
#pragma unroll
        for (int c = 0; c < 4; ++c)
            g_Z[(64*bi + ty*4 + r)*NN + 64*bj + tx*4 + c] -= acc[r][c];
}

// =====================================================================
__global__ void k_combine(float* __restrict__ out)
{
    __shared__ float z;
    if (threadIdx.x == 0) {
        float t = 0.f;
        for (int p = 0; p < 8; ++p) t += g_zpart[p];
        z = t;
    }
    __syncthreads();
    if (threadIdx.x < NBATCH)
        out[threadIdx.x] = g_bres[threadIdx.x] - z;
}

// =====================================================================
extern "C" void kernel_launch(void* const* d_in, const int* in_sizes, int n_in,
                              void* d_out, int out_size)
{
    const int* x = (const int*)d_in[0];
    const float* Bm = (const float*)d_in[1];
    if (in_sizes[0] == NN*NN && in_sizes[1] == NBATCH*NN) {
        x  = (const int*)d_in[1];
        Bm = (const float*)d_in[0];
    }
    float* out = (float*)d_out;

    cudaFuncSetAttribute(k_batch,  cudaFuncAttributeMaxDynamicSharedMemorySize, DYN_B);
    cudaFuncSetAttribute(k_zpanel, cudaFuncAttributeMaxDynamicSharedMemorySize, NN*65*4);

    k_gemm<<<dim3(8,8), 256>>>(Bm);
    k_batch<<<NBATCH, NTB, DYN_B>>>(x);
    for (int p = 0; p < 8; ++p) {
        int nr = NN - 64*p;
        k_zpanel<<<1, NT, nr*65*4>>>(p);
        int m = 7 - p;
        if (m > 0) k_ztrail<<<m*(m+1)/2, 256>>>(p);
    }
    k_combine<<<1, 128>>>(out);
}

// round 7
// speedup vs baseline: 2.3677x; 1.5418x over previous
#include <cuda_runtime.h>
#include <cuda_bf16.h>
#include <math.h>

#define NN 512
#define NBATCH 128
#define EPS 1e-8f
#define S_CAP 304
#define PK_CAP ((S_CAP*(S_CAP+1))/2)      /* 46360 floats = 185440 B */
#define PBW_SM (S_CAP-32)                  /* 272 */
#define PK_FULL ((NN*(NN+1))/2)
#define NTB 256                            /* k_batch threads */
#define NWB 8
#define NT 512                             /* k_zpanel threads */
#define NW 16
#define DYN_B ((PK_CAP + 32*PBW_SM)*4)    /* 220256 B */

// ---------------- device scratch ----------------
__device__ float g_L[NN*NN];
__device__ float g_Z[NN*NN];
__device__ float g_zpart[8];
__device__ float g_bres[NBATCH];
__device__ __align__(16) float g_fbA[(size_t)NBATCH * PK_FULL];
__device__ __align__(16) float g_fbPB[(size_t)NBATCH * 32 * NN];

// =====================================================================
// K1: L = B^T B + eps I ; Z = L + I.
// =====================================================================
__global__ __launch_bounds__(256) void k_gemm(const float* __restrict__ B)
{
    __shared__ float SA[16][64];
    __shared__ float SB[16][64];
    const int tid = threadIdx.x;
    const int tx = tid & 15, ty = tid >> 4;
    const int i0 = blockIdx.y * 64, j0 = blockIdx.x * 64;

    float acc[4][4];
#pragma unroll
    for (int r = 0; r < 4; ++r)
#pragma unroll
        for (int c = 0; c < 4; ++c) acc[r][c] = 0.f;

    for (int kc = 0; kc < NN; kc += 16) {
        for (int e = tid; e < 16*64; e += 256) {
            int kk = e >> 6, ii = e & 63;
            SA[kk][ii] = B[(kc+kk)*NN + i0 + ii];
            SB[kk][ii] = B[(kc+kk)*NN + j0 + ii];
        }
        __syncthreads();
#pragma unroll
        for (int kk = 0; kk < 16; ++kk) {
            float a[4], bb[4];
#pragma unroll
            for (int r = 0; r < 4; ++r) a[r]  = SA[kk][ty*4 + r];
#pragma unroll
            for (int c = 0; c < 4; ++c) bb[c] = SB[kk][tx*4 + c];
#pragma unroll
            for (int r = 0; r < 4; ++r)
#pragma unroll
                for (int c = 0; c < 4; ++c) acc[r][c] += a[r] * bb[c];
        }
        __syncthreads();
    }
#pragma unroll
    for (int r = 0; r < 4; ++r)
#pragma unroll
        for (int c = 0; c < 4; ++c) {
            int gi = i0 + ty*4 + r, gj = j0 + tx*4 + c;
            float v = acc[r][c] + ((gi == gj) ? EPS : 0.f);
            g_L[gi*NN + gj] = v;
            g_Z[gi*NN + gj] = v + ((gi == gj) ? 1.f : 0.f);
        }
}

// =====================================================================
// Per-batch blocked Cholesky (nb=32). Phase A fully unrolled (registers).
// =====================================================================
__global__ __launch_bounds__(NTB) void k_batch(const int* __restrict__ x)
{
    extern __shared__ float dynsm[];
    __shared__ int   sidx[NN];
    __shared__ short spos[NN];
    __shared__ unsigned char sact[NN];
    __shared__ float s_inv[32];
    __shared__ int   s_rbD[32];
    __shared__ int   s_sh;

    const int b = blockIdx.x;
    const int tid = threadIdx.x, warp = tid >> 5, lane = tid & 31;

    if (tid < 32) {
        int cnt = 0;
        for (int base = 0; base < NN; base += 32) {
            int g = base + lane;
            int v = (x[b*NN + g] != 0);
            unsigned m = __ballot_sync(0xffffffffu, v);
            int p = cnt + __popc(m & ((1u << lane) - 1u));
            if (v) sidx[p] = g;
            spos[g] = (short)p;
            sact[g] = (unsigned char)v;
            cnt += __popc(m);
        }
        if (lane == 0) s_sh = cnt;
    }
    __syncthreads();
    const int s = s_sh;
    const bool fits = (s <= S_CAP);
    float* A  = fits ? dynsm            : &g_fbA [(size_t)b * PK_FULL];
    float* PB = fits ? (dynsm + PK_CAP) : &g_fbPB[(size_t)b * 32 * NN];
    const int pbw = fits ? PBW_SM : NN;

    // gather: coalesced row read + compacting scatter
    for (int i = warp; i < s; i += NWB) {
        const float* Lrow = &g_L[sidx[i] * NN];
        const int rb = (i * (i + 1)) >> 1;
        const int glim = sidx[i] + 1;
        for (int g = lane; g < glim; g += 32) {
            float v = Lrow[g];
            if (sact[g]) A[rb + spos[g]] = v;
        }
    }
    __syncthreads();

    float lsum = 0.f;
    for (int j0 = 0; j0 < s; j0 += 32) {
        const int nbj = (s - j0 < 32) ? (s - j0) : 32;
        if (tid < nbj)
            s_rbD[tid] = (((j0 + tid) * (j0 + tid + 1)) >> 1) + j0;
        __syncthreads();

        // ---- Phase A: warp0, diag block, fully unrolled (registers) ----
        if (warp == 0) {
            const int row = j0 + lane;
            const bool act = (lane < nbj);
            const int rbI = act ? ((row * (row + 1)) >> 1) : 0;
            float v[32];
#pragma unroll
            for (int k = 0; k < 32; ++k)
                v[k] = (act && k <= lane && k < nbj) ? A[rbI + j0 + k] : 0.f;

#pragma unroll
            for (int j = 0; j < 32; ++j) {
                if (j >= nbj) break;
                float dj = __shfl_sync(0xffffffffu, v[j], j);
                float d = sqrtf(dj);
                float inv = 1.f / d;
                if (lane == j) { v[j] = d; s_inv[j] = inv; }
                else if (lane > j) v[j] *= inv;
                float cj = (lane > j) ? v[j] : 0.f;
#pragma unroll
                for (int k = j + 1; k < 32; ++k) {
                    float cjk = __shfl_sync(0xffffffffu, cj, k);
                    v[k] -= cj * cjk;
                }
                if (lane == 0) lsum += logf(d);
            }
#pragma unroll
            for (int k = 0; k < 32; ++k)
                if (act && k <= lane && k < nbj) A[rbI + j0 + k] = v[k];
        }
        __syncthreads();

        const int j1 = j0 + 32;
        if (j1 >= s) break;
        const int nrows = s - j1;

        // ---- Phase B: triangular solve; rows -> PB transposed ----
        for (int i = j1 + tid; i < s; i += NTB) {
            const int rbI = (i * (i + 1)) >> 1;
            float v[32];
#pragma unroll
            for (int j = 0; j < 32; ++j) v[j] = A[rbI + j0 + j];
#pragma unroll
            for (int j = 0; j < 32; ++j) {
                float acc0 = v[j], acc1 = 0.f;
                const float* dr = &A[s_rbD[j]];
#pragma unroll
                for (int m = 0; m + 1 < j; m += 2) {
                    acc0 -= v[m]   * dr[m];
                    acc1 -= v[m+1] * dr[m+1];
                }
                if (j & 1) acc0 -= v[j-1] * dr[j-1];
                v[j] = (acc0 + acc1) * s_inv[j];
            }
            const int col = i - j1;
#pragma unroll
            for (int j = 0; j < 32; ++j) PB[j * pbw + col] = v[j];
        }
        __syncthreads();

        // ---- Phase C: SYRK trailing from PB, 8x4 tiles, float4 LDS ----
        const int RT = (nrows + 7) >> 3;
        for (int ti = warp; ti < RT; ti += NWB) {
            const int ar = 8 * ti;
            const int ktmax = 2 * ti + 2;
            for (int kt = lane; kt < ktmax; kt += 32) {
                const int bc = 4 * kt;
                float acc[8][4];
#pragma unroll
                for (int qr = 0; qr < 8; ++qr)
#pragma unroll
                    for (int qc = 0; qc < 4; ++qc) acc[qr][qc] = 0.f;
#pragma unroll
                for (int j = 0; j < 32; ++j) {
                    const float* pr = &PB[j * pbw];
                    float4 a0 = *(const float4*)&pr[ar];
                    float4 a1 = *(const float4*)&pr[ar + 4];
                    float4 bv = *(const float4*)&pr[bc];
                    float av[8] = {a0.x,a0.y,a0.z,a0.w,a1.x,a1.y,a1.z,a1.w};
                    float bb[4] = {bv.x,bv.y,bv.z,bv.w};
#pragma unroll
                    for (int qr = 0; qr < 8; ++qr)
#pragma unroll
                        for (int qc = 0; qc < 4; ++qc)
                            acc[qr][qc] += av[qr] * bb[qc];
                }
#pragma unroll
                for (int qr = 0; qr < 8; ++qr) {
                    const int r = j1 + ar + qr;
                    if (r < s) {
                        const int rb = (r * (r + 1)) >> 1;
#pragma unroll
                        for (int qc = 0; qc < 4; ++qc) {
                            const int c = j1 + bc + qc;
                            if (c <= r) A[rb + c] -= acc[qr][qc];
                        }
                    }
                }
            }
        }
        __syncthreads();
    }
    if (tid == 0) g_bres[b] = 2.f * lsum;
}

// =====================================================================
// Z panel: Phase A fully unrolled.
// =====================================================================
__global__ __launch_bounds__(NT) void k_zpanel(int p)
{
    extern __shared__ float T[];              // nr x 65
    __shared__ float s_inv[32];
    const int nr = NN - 64 * p;
    const int tid = threadIdx.x, warp = tid >> 5, lane = tid & 31;

    for (int r = warp; r < nr; r += NW) {
        const float* src = &g_Z[(64*p + r)*NN + 64*p];
        float* dst = &T[r*65];
        for (int j = lane; j < 64; j += 32) dst[j] = src[j];
    }
    __syncthreads();

    float lsum = 0.f;
    for (int cb = 0; cb < 64; cb += 32) {
        // ---- Phase A ----
        if (warp == 0) {
            float v[32];
#pragma unroll
            for (int k = 0; k < 32; ++k)
                v[k] = (k <= lane) ? T[(cb+lane)*65 + cb + k] : 0.f;
#pragma unroll
            for (int j = 0; j < 32; ++j) {
                float dj = __shfl_sync(0xffffffffu, v[j], j);
                float d = sqrtf(dj);
                float inv = 1.f / d;
                if (lane == j) { v[j] = d; s_inv[j] = inv; }
                else if (lane > j) v[j] *= inv;
                float cj = (lane > j) ? v[j] : 0.f;
#pragma unroll
                for (int k = j + 1; k < 32; ++k) {
                    float cjk = __shfl_sync(0xffffffffu, cj, k);
                    v[k] -= cj * cjk;
                }
                if (lane == 0) lsum += logf(d);
            }
#pragma unroll
            for (int k = 0; k < 32; ++k)
                if (k <= lane) T[(cb+lane)*65 + cb + k] = v[k];
        }
        __syncthreads();

        const int r1 = cb + 32;
        // ---- Phase B ----
        for (int i = r1 + tid; i < nr; i += NT) {
            float* row = &T[i*65 + cb];
            float v[32];
#pragma unroll
            for (int j = 0; j < 32; ++j) v[j] = row[j];
#pragma unroll
            for (int j = 0; j < 32; ++j) {
                float acc0 = v[j], acc1 = 0.f;
                const float* dr = &T[(cb+j)*65 + cb];
#pragma unroll
                for (int m = 0; m + 1 < j; m += 2) {
                    acc0 -= v[m]   * dr[m];
                    acc1 -= v[m+1] * dr[m+1];
                }
                if (j & 1) acc0 -= v[j-1] * dr[j-1];
                v[j] = (acc0 + acc1) * s_inv[j];
            }
#pragma unroll
            for (int j = 0; j < 32; ++j) row[j] = v[j];
        }
        __syncthreads();

        // ---- Phase C (cb==0): rank-32 update of cols 32..63 ----
        if (cb == 0) {
            const int nrows = nr - 32;
            const int RT = (nrows + 15) >> 4;
            const int sub = lane >> 3;
            const int ktc = lane & 7;
            for (int ti = warp; ti < RT; ti += NW) {
                const int r0 = 32 + ti*16 + sub*4;
                const int c0 = 32 + ktc*4;
                float acc[4][4];
#pragma unroll
                for (int qr = 0; qr < 4; ++qr)
#pragma unroll
                    for (int qc = 0; qc < 4; ++qc) acc[qr][qc] = 0.f;
#pragma unroll
                for (int j = 0; j < 32; ++j) {
                    float a[4], bb[4];
#pragma unroll
                    for (int q = 0; q < 4; ++q) {
                        int r = r0 + q; if (r > nr - 1) r = nr - 1;
                        a[q] = T[r*65 + j];
                    }
#pragma unroll
                    for (int q = 0; q < 4; ++q) bb[q] = T[(c0+q)*65 + j];
#pragma unroll
                    for (int qr = 0; qr < 4; ++qr)
#pragma unroll
                        for (int qc = 0; qc < 4; ++qc)
                            acc[qr][qc] += a[qr] * bb[qc];
                }
#pragma unroll
                for (int qr = 0; qr < 4; ++qr) {
                    const int r = r0 + qr;
#pragma unroll
                    for (int qc = 0; qc < 4; ++qc) {
                        const int c = c0 + qc;
                        if (r < nr && c <= r)
                            T[r*65 + c] -= acc[qr][qc];
                    }
                }
            }
        }
        __syncthreads();
    }

    for (int r = warp; r < nr; r += NW) {
        float* dst = &g_Z[(64*p + r)*NN + 64*p];
        int jmax = (r < 63) ? r : 63;
        for (int j = lane; j <= jmax; j += 32) dst[j] = T[r*65 + j];
    }
    if (tid == 0) g_zpart[p] = 2.f * lsum;
}

__global__ __launch_bounds__(256) void k_ztrail(int p)
{
    __shared__ float As[64][65];
    __shared__ float Bs[64][65];
    int l = blockIdx.x, bi = 0, bj = 0;
    for (int q = p + 1; q <= 7; ++q) {
        int c = 8 - q;
        if (l < c) { bj = q; bi = q + l; break; }
        l -= c;
    }
    const int tid = threadIdx.x;
    const int tx = tid & 15, ty = tid >> 4;

    for (int e = tid; e < 64*64; e += 256) {
        int i = e >> 6, k = e & 63;
        As[i][k] = g_Z[(64*bi + i)*NN + 64*p + k];
    }
    for (int e = tid; e < 64*64; e += 256) {
        int i = e >> 6, k = e & 63;
        Bs[i][k] = g_Z[(64*bj + i)*NN + 64*p + k];
    }
    __syncthreads();

    float acc[4][4];
#pragma unroll
    for (int r = 0; r < 4; ++r)
#pragma unroll
        for (int c = 0; c < 4; ++c) acc[r][c] = 0.f;

    for (int k = 0; k < 64; ++k) {
        float a[4], bb[4];
#pragma unroll
        for (int r = 0; r < 4; ++r) a[r]  = As[ty*4 + r][k];
#pragma unroll
        for (int c = 0; c < 4; ++c) bb[c] = Bs[tx*4 + c][k];
#pragma unroll
        for (int r = 0; r < 4; ++r)
#pragma unroll
            for (int c = 0; c < 4; ++c) acc[r][c] += a[r] * bb[c];
    }
#pragma unroll
    for (int r = 0; r < 4; ++r)
#pragma unroll
        for (int c = 0; c < 4; ++c)
            g_Z[(64*bi + ty*4 + r)*NN + 64*bj + tx*4 + c] -= acc[r][c];
}

// =====================================================================
__global__ void k_combine(float* __restrict__ out)
{
    __shared__ float z;
    if (threadIdx.x == 0) {
        float t = 0.f;
        for (int p = 0; p < 8; ++p) t += g_zpart[p];
        z = t;
    }
    __syncthreads();
    if (threadIdx.x < NBATCH)
        out[threadIdx.x] = g_bres[threadIdx.x] - z;
}

// =====================================================================
extern "C" void kernel_launch(void* const* d_in, const int* in_sizes, int n_in,
                              void* d_out, int out_size)
{
    const int* x = (const int*)d_in[0];
    const float* Bm = (const float*)d_in[1];
    if (in_sizes[0] == NN*NN && in_sizes[1] == NBATCH*NN) {
        x  = (const int*)d_in[1];
        Bm = (const float*)d_in[0];
    }
    float* out = (float*)d_out;

    cudaFuncSetAttribute(k_batch,  cudaFuncAttributeMaxDynamicSharedMemorySize, DYN_B);
    cudaFuncSetAttribute(k_zpanel, cudaFuncAttributeMaxDynamicSharedMemorySize, NN*65*4);

    // Fork: Z chain on side stream s2, k_batch on main stream; join for combine.
    cudaStream_t s2;
    cudaStreamCreateWithFlags(&s2, cudaStreamNonBlocking);
    cudaEvent_t e1, e2;
    cudaEventCreateWithFlags(&e1, cudaEventDisableTiming);
    cudaEventCreateWithFlags(&e2, cudaEventDisableTiming);

    k_gemm<<<dim3(8,8), 256>>>(Bm);                       // #1 (main)
    cudaEventRecord(e1, 0);
    cudaStreamWaitEvent(s2, e1, 0);

    k_zpanel<<<1, NT, NN*65*4, s2>>>(0);                  // #2 (s2)
    k_ztrail<<<28, 256, 0, s2>>>(0);                      // #3 (s2)
    k_batch<<<NBATCH, NTB, DYN_B>>>(x);                   // #4 (main) <- profiled
    for (int p = 1; p < 8; ++p) {
        int nr = NN - 64*p;
        k_zpanel<<<1, NT, nr*65*4, s2>>>(p);
        int m = 7 - p;
        if (m > 0) k_ztrail<<<m*(m+1)/2, 256, 0, s2>>>(p);
    }
    cudaEventRecord(e2, s2);
    cudaStreamWaitEvent(0, e2, 0);
    k_combine<<<1, 128>>>(out);                           // last (main)

    // Destroy only when not capturing (capture-safe; leaks once per process
    // during the capture call, which allocates no device memory).
    cudaStreamCaptureStatus st = cudaStreamCaptureStatusNone;
    cudaStreamIsCapturing(0, &st);
    if (st == cudaStreamCaptureStatusNone) {
        cudaEventDestroy(e1);
        cudaEventDestroy(e2);
        cudaStreamDestroy(s2);
    }
}